// round 12
// baseline (speedup 1.0000x reference)
#include <cuda_runtime.h>

#define NBLK    128
#define TPBS    128      // scan threads per CTA
#define TPB     256      // gx/head threads
#define TSTEPS  128
#define BB      256
#define HH      256
#define INF     128
#define OUTF    128
#define G3H     768
#define M3B     768
#define RB      24       // rows per band
#define AP2     260      // sA row pitch (floats) — 1040B/row, 16B-aligned for cp.async
#define CT      32       // gate-cols per CTA

typedef unsigned long long ull;

// ---------------- device scratch ----------------
__device__ float g_gx[(size_t)TSTEPS * BB * G3H];   // x@Wx+bx, [t][b][3H]
__device__ float g_h0[M3B * HH];                    // ping-pong recurrent state
__device__ float g_h1[M3B * HH];
__device__ unsigned int g_bcnt[16 * 32];            // prologue pair barrier
__device__ unsigned int g_bgen[16 * 32];
__device__ unsigned int g_flag[32 * 8 * 32];        // per-(band,coltile) flags, 128B stride

// ---------------- helpers ----------------
__device__ __forceinline__ ull pack2(float v) {
    ull r; unsigned int u = __float_as_uint(v);
    asm("mov.b64 %0, {%1, %2};" : "=l"(r) : "r"(u), "r"(u));
    return r;
}
__device__ __forceinline__ void ffma2(ull& c, ull a, ull b) {
    asm("fma.rn.f32x2 %0, %1, %2, %0;" : "+l"(c) : "l"(a), "l"(b));
}
__device__ __forceinline__ float2 unpk(ull v) {
    float2 r; asm("mov.b64 {%0, %1}, %2;" : "=f"(r.x), "=f"(r.y) : "l"(v));
    return r;
}
union F4U { ull u[2]; float4 f; };

__device__ __forceinline__ float sigm(float x) {
    float e = __expf(-x);
    return __fdividef(1.0f, 1.0f + e);
}
__device__ __forceinline__ float tanh_fast(float x) {
    float ax = fabsf(x);
    float e  = __expf(-2.0f * ax);
    float t  = 1.0f - __fdividef(2.0f * e, 1.0f + e);
    return copysignf(t, x);
}
__device__ __forceinline__ void cpa16(unsigned int saddr, const void* gptr) {
    asm volatile("cp.async.cg.shared.global [%0], [%1], 16;" :: "r"(saddr), "l"(gptr) : "memory");
}
__device__ __forceinline__ unsigned int ld_acq(const unsigned int* p) {
    unsigned int v;
    asm volatile("ld.acquire.gpu.global.b32 %0, [%1];" : "=r"(v) : "l"(p) : "memory");
    return v;
}
__device__ __forceinline__ void st_rel(unsigned int* p, unsigned int v) {
    asm volatile("st.release.gpu.global.b32 [%0], %1;" :: "l"(p), "r"(v) : "memory");
}

// 8-participant pair barrier (prologue only)
__device__ __forceinline__ void pair_bar(int pair) {
    __syncthreads();
    if (threadIdx.x == 0) {
        unsigned int* cnt = &g_bcnt[pair * 32];
        volatile unsigned int* gen = (volatile unsigned int*)&g_bgen[pair * 32];
        unsigned int g = *gen;
        __threadfence();
        if (atomicAdd(cnt, 1u) == 7u) {
            *cnt = 0;
            __threadfence();
            *gen = g + 1;
        } else {
            while (*gen == g) { }
            __threadfence();
        }
    }
    __syncthreads();
}

// ---------------- phase 1: GX = X @ Wx + bx (R8 version, proven) ----------------
__global__ void __launch_bounds__(TPB) gx_kernel(const float* __restrict__ x,
                                                 const float* __restrict__ Wx,
                                                 const float* __restrict__ bx) {
    __shared__ float sX[64 * 68];
    __shared__ float sW[64 * 64];
    const int tid = threadIdx.x;
    const int m0 = blockIdx.x * 64;
    const int n0 = blockIdx.y * 64;
    const int tyr = (tid >> 4) << 2;
    const int txc = (tid & 15) << 2;

    ull acc[4][2];
#pragma unroll
    for (int i = 0; i < 4; ++i) { acc[i][0] = 0ULL; acc[i][1] = 0ULL; }

    for (int k0 = 0; k0 < INF; k0 += 64) {
        __syncthreads();
#pragma unroll
        for (int i = tid; i < 64 * 64; i += TPB) {
            int rl = i >> 6, kk = i & 63;
            int m = m0 + rl;
            int tt = m >> 8, bb2 = m & 255;
            sX[kk * 68 + rl] = x[bb2 * (TSTEPS * INF) + tt * INF + k0 + kk];
        }
#pragma unroll
        for (int i = tid; i < 64 * 64; i += TPB) {
            int kk = i >> 6, n = i & 63;
            sW[kk * 64 + n] = Wx[(k0 + kk) * G3H + n0 + n];
        }
        __syncthreads();
#pragma unroll 8
        for (int kk = 0; kk < 64; ++kk) {
            float4 a4 = *(const float4*)(sX + kk * 68 + tyr);
            ulonglong2 bv = *(const ulonglong2*)(sW + kk * 64 + txc);
            ull a;
            a = pack2(a4.x); ffma2(acc[0][0], a, bv.x); ffma2(acc[0][1], a, bv.y);
            a = pack2(a4.y); ffma2(acc[1][0], a, bv.x); ffma2(acc[1][1], a, bv.y);
            a = pack2(a4.z); ffma2(acc[2][0], a, bv.x); ffma2(acc[2][1], a, bv.y);
            a = pack2(a4.w); ffma2(acc[3][0], a, bv.x); ffma2(acc[3][1], a, bv.y);
        }
    }
    float4 bx4 = *(const float4*)(bx + n0 + txc);
#pragma unroll
    for (int i = 0; i < 4; ++i) {
        F4U cv; cv.u[0] = acc[i][0]; cv.u[1] = acc[i][1];
        cv.f.x += bx4.x; cv.f.y += bx4.y; cv.f.z += bx4.z; cv.f.w += bx4.w;
        *(float4*)(g_gx + (size_t)(m0 + tyr + i) * G3H + n0 + txc) = cv.f;
    }
}

// GEMM inner step over one packed k-pair index kp
#define GBODY(kp) { \
    float2 a0 = *(const float2*)(saty + 2 * (kp)); \
    float2 a1 = *(const float2*)(saty + AP2 + 2 * (kp)); \
    float2 a2 = *(const float2*)(saty + 2 * AP2 + 2 * (kp)); \
    const float* wb = sWh + (kp) * 192 + tx4; \
    ulonglong2 wR = *(const ulonglong2*)(wb); \
    ulonglong2 wZ = *(const ulonglong2*)(wb + 64); \
    ulonglong2 wN = *(const ulonglong2*)(wb + 128); \
    ull a; \
    a = pack2(a0.x); ffma2(acc[0][0], a, wR.x); ffma2(acc[0][1], a, wZ.x); ffma2(acc[0][2], a, wN.x); \
    a = pack2(a1.x); ffma2(acc[1][0], a, wR.x); ffma2(acc[1][1], a, wZ.x); ffma2(acc[1][2], a, wN.x); \
    a = pack2(a2.x); ffma2(acc[2][0], a, wR.x); ffma2(acc[2][1], a, wZ.x); ffma2(acc[2][2], a, wN.x); \
    a = pack2(a0.y); ffma2(acc[0][0], a, wR.y); ffma2(acc[0][1], a, wZ.y); ffma2(acc[0][2], a, wN.y); \
    a = pack2(a1.y); ffma2(acc[1][0], a, wR.y); ffma2(acc[1][1], a, wZ.y); ffma2(acc[1][2], a, wN.y); \
    a = pack2(a2.y); ffma2(acc[2][0], a, wR.y); ffma2(acc[2][1], a, wZ.y); ffma2(acc[2][2], a, wN.y); \
}

// ---------------- phase 2: persistent scan, 32 bands x 8 CTAs, 2 bands per CTA ----------------
// smem (floats): sWh[24576] | sA0[24*260] | sA1[24*260] | sGx0[2*2304] | sGx1[2*2304]
__global__ void __launch_bounds__(TPBS, 1)
cru_persistent(const float* __restrict__ hid,
               const float* __restrict__ Wh,
               const float* __restrict__ bh) {
    extern __shared__ float smem[];
    float* sWh  = smem;
    float* sA0  = smem + 24576;
    float* sA1  = sA0 + RB * AP2;
    float* sGx0 = sA1 + RB * AP2;
    float* sGx1 = sGx0 + 2 * RB * 96;

    const int tid = threadIdx.x;
    const int bid = blockIdx.x;
    const int pair = bid >> 3;
    const int j    = bid & 7;
    const int band0 = 2 * pair, band1 = 2 * pair + 1;
    const int rm0 = band0 * RB;            // = pair*48
    const int rm1 = rm0 + RB;
    const int k0  = j * CT;
    const int cbase = j * 8;               // own 16B-chunk base
    const int ty = tid >> 4, tx = tid & 15;
    const int ty3 = ty * 3, tx2 = tx * 2, tx4 = tx * 4;
    const unsigned int sA0_b  = (unsigned int)__cvta_generic_to_shared(sA0);
    const unsigned int sA1_b  = (unsigned int)__cvta_generic_to_shared(sA1);
    const unsigned int sGx0_b = (unsigned int)__cvta_generic_to_shared(sGx0);
    const unsigned int sGx1_b = (unsigned int)__cvta_generic_to_shared(sGx1);
    unsigned int* myflag0 = &g_flag[(band0 * 8 + j) * 32];
    unsigned int* myflag1 = &g_flag[(band1 * 8 + j) * 32];
    const unsigned int E0 = *myflag0;      // epochs (own flags; monotonic)
    const unsigned int E1 = *myflag1;

    // packed Wh slice: sWh[kp*192 + g*64 + tx*4 + {(2kp,c0),(2kp,c1),(2kp+1,c0),(2kp+1,c1)}]
    for (int i = tid; i < 24576; i += TPBS) {
        int kp = i / 192, r = i - kp * 192;
        int g = r >> 6, q = r & 63;
        int txi = q >> 2, jj = q & 3;
        int kk = 2 * kp + (jj >> 1);
        int c  = txi * 2 + (jj & 1);
        sWh[i] = Wh[kk * G3H + g * HH + k0 + c];
    }
    // init own slabs of h_0 for both bands (48 contiguous rows x own 32 cols)
    for (int c = tid; c < 768; c += TPBS) {          // 768 float2
        int row = c >> 4, f = (c & 15) << 1;
        *(float2*)&g_h0[(rm0 + row) * HH + k0 + f] =
            *(const float2*)&hid[(rm0 + row) * HH + k0 + f];
    }
    pair_bar(pair);   // all slabs of h_0 for both bands written

    // prologue group P: full sA0/sA1 fills (h_0) + sGx0 buf0 (gx[0] for band0)
#pragma unroll
    for (int it = 0; it < 12; ++it) {
        int c = tid + TPBS * it;                     // 1536 chunks per band
        int row = c >> 6, f = (c & 63) << 2;
        cpa16(sA0_b + (unsigned)((row * AP2 + f) << 2), g_h0 + (rm0 + row) * HH + f);
        cpa16(sA1_b + (unsigned)((row * AP2 + f) << 2), g_h0 + (rm1 + row) * HH + f);
    }
    for (int c = tid; c < 576; c += TPBS) {
        int row = c / 24, q = c - row * 24;
        int seg = q >> 3, f0 = (q & 7) << 2;
        int b = (rm0 + row) & 255;
        cpa16(sGx0_b + (unsigned)((row * 96 + seg * 32 + f0) << 2),
              g_gx + (size_t)b * G3H + seg * HH + k0 + f0);
    }
    asm volatile("cp.async.commit_group;" ::: "memory");
    asm volatile("cp.async.wait_group 0;" ::: "memory");
    __syncthreads();

    const float bhr0 = bh[k0 + tx2],          bhr1 = bh[k0 + tx2 + 1];
    const float bhz0 = bh[HH + k0 + tx2],     bhz1 = bh[HH + k0 + tx2 + 1];
    const float bhn0 = bh[2 * HH + k0 + tx2], bhn1 = bh[2 * HH + k0 + tx2 + 1];

    // hold registers per band
    float2 hold0[3], hold1[3];
#pragma unroll
    for (int r = 0; r < 3; ++r) {
        hold0[r] = *(const float2*)(sA0 + (ty3 + r) * AP2 + k0 + tx2);
        hold1[r] = *(const float2*)(sA1 + (ty3 + r) * AP2 + k0 + tx2);
    }

    for (int t = 0; t < TSTEPS; ++t) {
        const float* hin  = (t & 1) ? g_h1 : g_h0;   // h_t
        float*       hout = (t & 1) ? g_h0 : g_h1;   // h_{t+1}
        const int buf = t & 1;

        // ================= PHASE A: band0 compute, band1 stage =================
        // wait band1 h_t slabs (released one full phase ago -> usually free)
        if (tid < 32) {
            bool done = (tid >= 8);
            const unsigned int* f = &g_flag[(band1 * 8 + (tid & 7)) * 32];
            unsigned int want = E1 + (unsigned)t;
            do { if (!done) done = ((int)(ld_acq(f) - want) >= 0); } while (!__all_sync(0xffffffffu, done));
        }
        __syncthreads();
        // group R1: refill sA1 other-slabs (h_t) + gx1[t] into sGx1 buf
        for (int c = tid; c < 1344; c += TPBS) {      // 24 rows x 56 chunks
            int row = c / 56, q = c - row * 56;
            int f = ((cbase + 8 + q) & 63) << 2;
            cpa16(sA1_b + (unsigned)((row * AP2 + f) << 2), hin + (rm1 + row) * HH + f);
        }
        {
            const float* gxb = g_gx + (size_t)t * BB * G3H;
            for (int c = tid; c < 576; c += TPBS) {
                int row = c / 24, q = c - row * 24;
                int seg = q >> 3, f0 = (q & 7) << 2;
                int b = (rm1 + row) & 255;
                cpa16(sGx1_b + (unsigned)((buf * 2304 + row * 96 + seg * 32 + f0) << 2),
                      gxb + (size_t)b * G3H + seg * HH + k0 + f0);
            }
        }
        asm volatile("cp.async.commit_group;" ::: "memory");
        // drain previous R0' (sA0 h_t + gx0[t]); leave R1 in flight
        asm volatile("cp.async.wait_group 1;" ::: "memory");
        __syncthreads();

        // GEMM band0 (full 128 kp)
        {
            ull acc[3][3];
#pragma unroll
            for (int r = 0; r < 3; ++r) { acc[r][0] = 0ULL; acc[r][1] = 0ULL; acc[r][2] = 0ULL; }
            const float* saty = sA0 + ty3 * AP2;
#pragma unroll 4
            for (int kp = 0; kp < 128; ++kp) GBODY(kp);

            // update band0
#pragma unroll
            for (int r = 0; r < 3; ++r) {
                float2 Gr = unpk(acc[r][0]);
                float2 Gz = unpk(acc[r][1]);
                float2 Gn = unpk(acc[r][2]);
                const float* gp = sGx0 + buf * 2304 + (ty3 + r) * 96 + tx2;
                float2 gxr = *(const float2*)(gp);
                float2 gxz = *(const float2*)(gp + 32);
                float2 gxn = *(const float2*)(gp + 64);
                float R0 = sigm(gxr.x + Gr.x + bhr0);
                float R1 = sigm(gxr.y + Gr.y + bhr1);
                float Z0 = sigm(gxz.x + Gz.x + bhz0);
                float Z1 = sigm(gxz.y + Gz.y + bhz1);
                float N0 = tanh_fast(gxn.x + R0 * (Gn.x + bhn0));
                float N1 = tanh_fast(gxn.y + R1 * (Gn.y + bhn1));
                float2 hn;
                hn.x = N0 + Z0 * (hold0[r].x - N0);
                hn.y = N1 + Z1 * (hold0[r].y - N1);
                hold0[r] = hn;
                *(float2*)(sA0 + (ty3 + r) * AP2 + k0 + tx2) = hn;
                __stcg((float2*)(hout + (rm0 + ty3 + r) * HH + k0 + tx2), hn);
            }
        }
        __syncthreads();
        if (tid == 0) st_rel(myflag0, E0 + (unsigned)(t + 1));

        // ================= PHASE B: band1 compute, band0 stage =================
        // wait band0 h_{t+1} slabs (peers just released at their phase A end)
        if (tid < 32) {
            bool done = (tid >= 8);
            const unsigned int* f = &g_flag[(band0 * 8 + (tid & 7)) * 32];
            unsigned int want = E0 + (unsigned)(t + 1);
            do { if (!done) done = ((int)(ld_acq(f) - want) >= 0); } while (!__all_sync(0xffffffffu, done));
        }
        __syncthreads();
        // group R0': refill sA0 other-slabs (h_{t+1}) + gx0[t+1] into other sGx0 buf
        if (t + 1 < TSTEPS) {
            const float* hnx = (t & 1) ? g_h0 : g_h1;     // h_{t+1} buffer
            for (int c = tid; c < 1344; c += TPBS) {
                int row = c / 56, q = c - row * 56;
                int f = ((cbase + 8 + q) & 63) << 2;
                cpa16(sA0_b + (unsigned)((row * AP2 + f) << 2), hnx + (rm0 + row) * HH + f);
            }
            const float* gxb = g_gx + (size_t)(t + 1) * BB * G3H;
            for (int c = tid; c < 576; c += TPBS) {
                int row = c / 24, q = c - row * 24;
                int seg = q >> 3, f0 = (q & 7) << 2;
                int b = (rm0 + row) & 255;
                cpa16(sGx0_b + (unsigned)((((buf ^ 1) * 2304) + row * 96 + seg * 32 + f0) << 2),
                      gxb + (size_t)b * G3H + seg * HH + k0 + f0);
            }
        }
        asm volatile("cp.async.commit_group;" ::: "memory");
        // drain R1 (sA1 h_t + gx1[t]); leave R0' in flight
        asm volatile("cp.async.wait_group 1;" ::: "memory");
        __syncthreads();

        // GEMM band1 (full 128 kp)
        {
            ull acc[3][3];
#pragma unroll
            for (int r = 0; r < 3; ++r) { acc[r][0] = 0ULL; acc[r][1] = 0ULL; acc[r][2] = 0ULL; }
            const float* saty = sA1 + ty3 * AP2;
#pragma unroll 4
            for (int kp = 0; kp < 128; ++kp) GBODY(kp);

            // update band1
#pragma unroll
            for (int r = 0; r < 3; ++r) {
                float2 Gr = unpk(acc[r][0]);
                float2 Gz = unpk(acc[r][1]);
                float2 Gn = unpk(acc[r][2]);
                const float* gp = sGx1 + buf * 2304 + (ty3 + r) * 96 + tx2;
                float2 gxr = *(const float2*)(gp);
                float2 gxz = *(const float2*)(gp + 32);
                float2 gxn = *(const float2*)(gp + 64);
                float R0 = sigm(gxr.x + Gr.x + bhr0);
                float R1 = sigm(gxr.y + Gr.y + bhr1);
                float Z0 = sigm(gxz.x + Gz.x + bhz0);
                float Z1 = sigm(gxz.y + Gz.y + bhz1);
                float N0 = tanh_fast(gxn.x + R0 * (Gn.x + bhn0));
                float N1 = tanh_fast(gxn.y + R1 * (Gn.y + bhn1));
                float2 hn;
                hn.x = N0 + Z0 * (hold1[r].x - N0);
                hn.y = N1 + Z1 * (hold1[r].y - N1);
                hold1[r] = hn;
                *(float2*)(sA1 + (ty3 + r) * AP2 + k0 + tx2) = hn;
                __stcg((float2*)(hout + (rm1 + ty3 + r) * HH + k0 + tx2), hn);
            }
        }
        __syncthreads();
        if (tid == 0) st_rel(myflag1, E1 + (unsigned)(t + 1));
    }
    asm volatile("cp.async.wait_group 0;" ::: "memory");   // nothing pending at exit
}

// ---------------- phase 3: output head (h_128 in g_h0) ----------------
__global__ void __launch_bounds__(TPB) head_kernel(const float* __restrict__ Wf,
                                                   const float* __restrict__ bf,
                                                   float* __restrict__ out) {
    const int bid = blockIdx.x;
    const int tid = threadIdx.x;
    if (bid < 128) {
        __shared__ float s[2][256];
        int rb0 = bid << 1;
#pragma unroll
        for (int jj = 0; jj < 2; ++jj)
            s[jj][tid] = __ldcg(&g_h0[(rb0 + jj) * HH + tid])
                       + __ldcg(&g_h0[(256 + rb0 + jj) * HH + tid])
                       + __ldcg(&g_h0[(512 + rb0 + jj) * HH + tid]);
        __syncthreads();
        int r = tid >> 7, o = tid & 127;
        float acc = bf[o];
        const float* sr = s[r];
#pragma unroll 8
        for (int k = 0; k < HH; ++k)
            acc = fmaf(sr[k], __ldg(Wf + k * OUTF + o), acc);
        out[(rb0 + r) * OUTF + o] = (acc > 0.0f) ? acc : expm1f(acc);
    } else {
        int c = bid - 128;
        float acc = 0.0f;
#pragma unroll 8
        for (int b2 = 0; b2 < BB; ++b2)
            acc += __ldcg(&g_h0[(c * 256 + b2) * HH + tid]);
        out[BB * OUTF + c * HH + tid] = acc * (1.0f / 256.0f);
    }
}

// ---------------- launch ----------------
extern "C" void kernel_launch(void* const* d_in, const int* in_sizes, int n_in,
                              void* d_out, int out_size) {
    const float* x   = (const float*)d_in[0];
    const float* hid = (const float*)d_in[1];
    const float* Wx  = (const float*)d_in[2];
    const float* bx  = (const float*)d_in[3];
    const float* Wh  = (const float*)d_in[4];
    const float* bh  = (const float*)d_in[5];
    const float* Wf  = (const float*)d_in[6];
    const float* bf  = (const float*)d_in[7];
    float* out = (float*)d_out;

    const int smem_p = (24576 + 2 * RB * AP2 + 4 * RB * 96) * (int)sizeof(float); // 185472
    cudaFuncSetAttribute(cru_persistent, cudaFuncAttributeMaxDynamicSharedMemorySize, smem_p);

    gx_kernel<<<dim3(512, 12), TPB>>>(x, Wx, bx);
    cru_persistent<<<NBLK, TPBS, smem_p>>>(hid, Wh, bh);
    head_kernel<<<131, TPB>>>(Wf, bf, out);
}